// round 1
// baseline (speedup 1.0000x reference)
#include <cuda_runtime.h>
#include <math.h>

#define N_NODES 100000
#define N_EDGES 3200000
#define F_IN    256
#define U       32
#define C       40

// ---- scratch (no allocations allowed) ----
__device__ float g_degout[N_NODES];
__device__ float g_degin[N_NODES];
__device__ float g_invout[N_NODES];
__device__ float g_invin[N_NODES];
__device__ float g_h1[(size_t)N_NODES * U];    // h1 = (x*d_out)@W1, later reused for relu'd layer-1 output
__device__ float g_agg1[(size_t)N_NODES * U];
__device__ float g_h2[(size_t)N_NODES * C];

// ---------------------------------------------------------------------------
// Zero all accumulators (d_out is poisoned by harness; it is layer-2 accumulator)
__global__ void zero_kernel(float* __restrict__ out) {
    const int stride = gridDim.x * blockDim.x;
    int t = blockIdx.x * blockDim.x + threadIdx.x;
    for (int i = t; i < N_NODES; i += stride) { g_degout[i] = 0.f; g_degin[i] = 0.f; }
    for (int i = t; i < N_NODES * U; i += stride) g_agg1[i] = 0.f;
    for (int i = t; i < N_NODES * C; i += stride) out[i] = 0.f;
}

// ---------------------------------------------------------------------------
__global__ void degree_kernel(const int* __restrict__ src, const int* __restrict__ dst) {
    int e = blockIdx.x * blockDim.x + threadIdx.x;
    if (e >= N_EDGES) return;
    atomicAdd(&g_degout[src[e]], 1.0f);
    atomicAdd(&g_degin[dst[e]], 1.0f);
}

__global__ void invsqrt_kernel() {
    int n = blockIdx.x * blockDim.x + threadIdx.x;
    if (n >= N_NODES) return;
    g_invout[n] = rsqrtf(fmaxf(g_degout[n], 1.0f));
    g_invin[n]  = rsqrtf(fmaxf(g_degin[n],  1.0f));
}

// ---------------------------------------------------------------------------
// h1[n, u] = inv_out[n] * sum_k x[n,k] * W1[k,u]
// One warp per node. W1 (256x32 = 32KB) staged in shared; x row held in
// registers (8 per lane) and broadcast via shfl.
__global__ void gemm1_kernel(const float* __restrict__ x, const float* __restrict__ W1) {
    __shared__ float sW[F_IN * U];
    const int tid = threadIdx.x;
    for (int i = tid; i < F_IN * U; i += blockDim.x) sW[i] = W1[i];
    __syncthreads();

    const int warp = tid >> 5, lane = tid & 31;
    const int n = blockIdx.x * 8 + warp;
    if (n >= N_NODES) return;

    const float scale = g_invout[n];
    const float* xr = x + (size_t)n * F_IN;
    float xv[8];
#pragma unroll
    for (int i = 0; i < 8; i++) xv[i] = xr[lane + 32 * i];

    float acc0 = 0.f, acc1 = 0.f;
#pragma unroll
    for (int i = 0; i < 8; i++) {
#pragma unroll
        for (int j = 0; j < 32; j += 2) {
            float v0 = __shfl_sync(0xffffffffu, xv[i], j);
            float v1 = __shfl_sync(0xffffffffu, xv[i], j + 1);
            acc0 += v0 * sW[(i * 32 + j) * U + lane];
            acc1 += v1 * sW[(i * 32 + j + 1) * U + lane];
        }
    }
    g_h1[(size_t)n * U + lane] = (acc0 + acc1) * scale;
}

// ---------------------------------------------------------------------------
// Layer-1 scatter: one warp per edge, lane = feature (32 features).
__global__ void scatter1_kernel(const int* __restrict__ src, const int* __restrict__ dst) {
    const unsigned t = blockIdx.x * blockDim.x + threadIdx.x;
    const unsigned e = t >> 5;
    const int lane = t & 31;
    if (e >= N_EDGES) return;
    const int s = src[e];
    const int d = dst[e];
    const float v = g_h1[(size_t)s * U + lane];
    atomicAdd(&g_agg1[(size_t)d * U + lane], v);
}

// out1 = relu(agg1 * inv_in + b1), written back into g_h1 (h1 is dead now)
__global__ void post1_kernel(const float* __restrict__ b1) {
    int i = blockIdx.x * blockDim.x + threadIdx.x;
    if (i >= N_NODES * U) return;
    const int n = i >> 5;       // U == 32
    const int u = i & 31;
    g_h1[i] = fmaxf(g_agg1[i] * g_invin[n] + b1[u], 0.f);
}

// ---------------------------------------------------------------------------
// h2[n, j] = inv_out[n] * sum_k h1r[n,k] * W2[k,j]   (K=32, J=40)
__global__ void gemm2_kernel(const float* __restrict__ W2) {
    int idx = blockIdx.x * blockDim.x + threadIdx.x;
    if (idx >= N_NODES * C) return;
    const int n = idx / C;
    const int j = idx - n * C;
    const float* h = &g_h1[(size_t)n * U];
    float acc = 0.f;
#pragma unroll
    for (int k = 0; k < U; k++)
        acc += h[k] * __ldg(&W2[k * C + j]);
    g_h2[idx] = acc * g_invout[n];
}

// ---------------------------------------------------------------------------
// Layer-2 scatter: thread per (edge, feature), 40 features wide, into d_out.
__global__ void scatter2_kernel(const int* __restrict__ src, const int* __restrict__ dst,
                                float* __restrict__ out) {
    const unsigned t = blockIdx.x * blockDim.x + threadIdx.x;
    if (t >= (unsigned)N_EDGES * C) return;
    const unsigned e = t / C;
    const int j = t - e * C;
    const int s = src[e];
    const int d = dst[e];
    atomicAdd(&out[(size_t)d * C + j], g_h2[(size_t)s * C + j]);
}

// ---------------------------------------------------------------------------
// Final: out = log_softmax(agg2 * inv_in + b2). One warp per node (40 cols:
// lanes 0..31 handle col=lane, lanes 0..7 also handle col=32+lane).
__global__ void final_kernel(float* __restrict__ out, const float* __restrict__ b2) {
    const int gwarp = (blockIdx.x * blockDim.x + threadIdx.x) >> 5;
    const int lane = threadIdx.x & 31;
    if (gwarp >= N_NODES) return;
    const float s = g_invin[gwarp];
    float* row = out + (size_t)gwarp * C;

    float v0 = row[lane] * s + b2[lane];
    float v1 = (lane < 8) ? (row[32 + lane] * s + b2[32 + lane]) : -1e30f;

    float m = fmaxf(v0, v1);
#pragma unroll
    for (int o = 16; o; o >>= 1) m = fmaxf(m, __shfl_xor_sync(0xffffffffu, m, o));

    float se = expf(v0 - m) + ((lane < 8) ? expf(v1 - m) : 0.f);
#pragma unroll
    for (int o = 16; o; o >>= 1) se += __shfl_xor_sync(0xffffffffu, se, o);

    const float ls = logf(se);
    row[lane] = v0 - m - ls;
    if (lane < 8) row[32 + lane] = v1 - m - ls;
}

// ---------------------------------------------------------------------------
extern "C" void kernel_launch(void* const* d_in, const int* in_sizes, int n_in,
                              void* d_out, int out_size) {
    const float* x   = (const float*)d_in[0];
    const float* W1  = (const float*)d_in[1];
    const float* b1  = (const float*)d_in[2];
    const float* W2  = (const float*)d_in[3];
    const float* b2  = (const float*)d_in[4];
    const int*   src = (const int*)d_in[5];
    const int*   dst = (const int*)d_in[6];
    float* out = (float*)d_out;

    zero_kernel<<<2048, 256>>>(out);
    degree_kernel<<<(N_EDGES + 255) / 256, 256>>>(src, dst);
    invsqrt_kernel<<<(N_NODES + 255) / 256, 256>>>();
    gemm1_kernel<<<(N_NODES + 7) / 8, 256>>>(x, W1);
    {
        unsigned total = (unsigned)N_EDGES * 32u;
        scatter1_kernel<<<(total + 255) / 256, 256>>>(src, dst);
    }
    post1_kernel<<<(N_NODES * U + 255) / 256, 256>>>(b1);
    gemm2_kernel<<<(N_NODES * C + 255) / 256, 256>>>(W2);
    {
        unsigned total = (unsigned)N_EDGES * (unsigned)C;
        scatter2_kernel<<<(total + 255) / 256, 256>>>(src, dst, out);
    }
    final_kernel<<<(N_NODES * 32 + 255) / 256, 256>>>(out, b2);
}

// round 4
// speedup vs baseline: 1.9191x; 1.9191x over previous
#include <cuda_runtime.h>
#include <math.h>

#define N_NODES 100000
#define N_EDGES 3200000
#define F_IN    256
#define U       32
#define C       40

// ---- scratch (device globals; no allocations allowed) ----
__device__ int   g_degout_i[N_NODES];
__device__ int   g_degin_i[N_NODES];
__device__ float g_invout[N_NODES];
__device__ float g_invin[N_NODES];
__device__ int   g_off[N_NODES + 1];     // CSR offsets by dst
__device__ int   g_cursor[N_NODES];      // fill cursors
__device__ int   g_esrc[N_EDGES];        // src ids sorted by dst
__device__ float g_h1[(size_t)N_NODES * U];   // (x * d_out^-1/2) @ W1
__device__ float g_h1r[(size_t)N_NODES * U];  // relu(layer1 out)
__device__ float g_h2[(size_t)N_NODES * C];   // (h1r * d_out^-1/2) @ W2

// ---------------------------------------------------------------------------
__global__ void zero_deg_kernel() {
    int i = blockIdx.x * blockDim.x + threadIdx.x;
    if (i < N_NODES) { g_degout_i[i] = 0; g_degin_i[i] = 0; }
}

__global__ void hist_kernel(const int* __restrict__ src, const int* __restrict__ dst) {
    int e = blockIdx.x * blockDim.x + threadIdx.x;
    if (e >= N_EDGES) return;
    atomicAdd(&g_degout_i[src[e]], 1);
    atomicAdd(&g_degin_i[dst[e]], 1);
}

__global__ void invsqrt_kernel() {
    int n = blockIdx.x * blockDim.x + threadIdx.x;
    if (n >= N_NODES) return;
    g_invout[n] = rsqrtf(fmaxf((float)g_degout_i[n], 1.0f));
    g_invin[n]  = rsqrtf(fmaxf((float)g_degin_i[n],  1.0f));
}

// ---------------------------------------------------------------------------
// Single-block exclusive prefix scan over in-degrees -> CSR offsets + cursors.
__global__ void scan_kernel() {
    __shared__ int s[1024];
    const int t = threadIdx.x;
    const int CH = (N_NODES + 1023) / 1024;   // 98
    const int lo = t * CH;
    const int hi = min(lo + CH, N_NODES);

    int sum = 0;
    for (int i = lo; i < hi; i++) sum += g_degin_i[i];
    s[t] = sum;
    __syncthreads();
    for (int off = 1; off < 1024; off <<= 1) {
        int v = (t >= off) ? s[t - off] : 0;
        __syncthreads();
        s[t] += v;
        __syncthreads();
    }
    int run = (t == 0) ? 0 : s[t - 1];
    for (int i = lo; i < hi; i++) {
        g_off[i] = run;
        g_cursor[i] = run;
        run += g_degin_i[i];
    }
    if (t == 1023) g_off[N_NODES] = run;   // == N_EDGES
}

__global__ void reorder_kernel(const int* __restrict__ src, const int* __restrict__ dst) {
    int e = blockIdx.x * blockDim.x + threadIdx.x;
    if (e >= N_EDGES) return;
    int pos = atomicAdd(&g_cursor[dst[e]], 1);
    g_esrc[pos] = src[e];
}

// ---------------------------------------------------------------------------
// GEMM1: h1[n,u] = invout[n] * sum_k x[n,k]*W1[k,u]
// Register-blocked: block = 128 threads, tile = 64 nodes x 32 u, K tiled by 64.
// Each thread computes a 4(node) x 4(u) outer product per k.
#define TILE_N 64
#define KT     64
__global__ void __launch_bounds__(128) gemm1_kernel(const float* __restrict__ x,
                                                    const float* __restrict__ W1) {
    __shared__ float sX[TILE_N][KT + 1];   // +1 pad: conflict-free column reads
    __shared__ float sW[KT][U];

    const int t  = threadIdx.x;
    const int ug = t & 7;        // u-group: u = ug*4 .. ug*4+3
    const int ng = t >> 3;       // node-group: n = ng*4 .. ng*4+3
    const int n0 = blockIdx.x * TILE_N;

    float acc[4][4] = {};

    for (int k0 = 0; k0 < F_IN; k0 += KT) {
        for (int i = t; i < KT * U; i += 128)
            ((float*)sW)[i] = W1[k0 * U + i];
        for (int i = t; i < TILE_N * KT; i += 128) {
            int n = i >> 6;          // /KT
            int k = i & (KT - 1);
            int gn = n0 + n;
            sX[n][k] = (gn < N_NODES) ? x[(size_t)gn * F_IN + k0 + k] : 0.f;
        }
        __syncthreads();
#pragma unroll
        for (int k = 0; k < KT; k++) {
            float4 w = *(const float4*)&sW[k][ug * 4];
            float xv0 = sX[ng * 4 + 0][k];
            float xv1 = sX[ng * 4 + 1][k];
            float xv2 = sX[ng * 4 + 2][k];
            float xv3 = sX[ng * 4 + 3][k];
            acc[0][0] += xv0 * w.x; acc[0][1] += xv0 * w.y; acc[0][2] += xv0 * w.z; acc[0][3] += xv0 * w.w;
            acc[1][0] += xv1 * w.x; acc[1][1] += xv1 * w.y; acc[1][2] += xv1 * w.z; acc[1][3] += xv1 * w.w;
            acc[2][0] += xv2 * w.x; acc[2][1] += xv2 * w.y; acc[2][2] += xv2 * w.z; acc[2][3] += xv2 * w.w;
            acc[3][0] += xv3 * w.x; acc[3][1] += xv3 * w.y; acc[3][2] += xv3 * w.z; acc[3][3] += xv3 * w.w;
        }
        __syncthreads();
    }

#pragma unroll
    for (int i = 0; i < 4; i++) {
        int n = n0 + ng * 4 + i;
        if (n < N_NODES) {
            float s = g_invout[n];
            float4 o;
            o.x = acc[i][0] * s; o.y = acc[i][1] * s;
            o.z = acc[i][2] * s; o.w = acc[i][3] * s;
            *(float4*)&g_h1[(size_t)n * U + ug * 4] = o;
        }
    }
}

// ---------------------------------------------------------------------------
// Aggregation layer 1 (gather over CSR) + norm + bias + relu, fused.
// One warp per node; lane = feature.
__global__ void agg1_kernel(const float* __restrict__ b1) {
    const int n = (blockIdx.x * blockDim.x + threadIdx.x) >> 5;
    const int lane = threadIdx.x & 31;
    if (n >= N_NODES) return;
    const int start = g_off[n], end = g_off[n + 1];

    float acc = 0.f;
    int e = start;
    while (e + 32 <= end) {
        int sv = g_esrc[e + lane];
        float a0 = 0.f, a1 = 0.f, a2 = 0.f, a3 = 0.f;
#pragma unroll
        for (int i = 0; i < 32; i += 4) {
            int s0 = __shfl_sync(0xffffffffu, sv, i);
            int s1 = __shfl_sync(0xffffffffu, sv, i + 1);
            int s2 = __shfl_sync(0xffffffffu, sv, i + 2);
            int s3 = __shfl_sync(0xffffffffu, sv, i + 3);
            a0 += g_h1[(size_t)s0 * U + lane];
            a1 += g_h1[(size_t)s1 * U + lane];
            a2 += g_h1[(size_t)s2 * U + lane];
            a3 += g_h1[(size_t)s3 * U + lane];
        }
        acc += (a0 + a1) + (a2 + a3);
        e += 32;
    }
    if (e < end) {
        int rem = end - e;
        int sv = (lane < rem) ? g_esrc[e + lane] : 0;
        for (int i = 0; i < rem; i++) {
            int s = __shfl_sync(0xffffffffu, sv, i);
            acc += g_h1[(size_t)s * U + lane];
        }
    }
    g_h1r[(size_t)n * U + lane] = fmaxf(acc * g_invin[n] + b1[lane], 0.f);
}

// ---------------------------------------------------------------------------
// GEMM2: h2[n,j] = invout[n] * sum_k h1r[n,k]*W2[k,j]   (K=32, J=40)
// Block handles 32 nodes; thread = (node = t&31, 5 feats at j0=(t>>5)*5).
__global__ void __launch_bounds__(256) gemm2_kernel(const float* __restrict__ W2) {
    __shared__ float sH[32][U + 1];
    __shared__ float sW2[U * C];
    const int t = threadIdx.x;
    const int n0 = blockIdx.x * 32;

    for (int i = t; i < U * C; i += 256) sW2[i] = W2[i];
    for (int i = t; i < 32 * U; i += 256) {
        int n = i >> 5, k = i & 31;
        sH[n][k] = g_h1r[(size_t)(n0 + n) * U + k];
    }
    __syncthreads();

    const int n = t & 31;
    const int j0 = (t >> 5) * 5;
    float acc[5] = {};
#pragma unroll
    for (int k = 0; k < U; k++) {
        float xv = sH[n][k];
#pragma unroll
        for (int j = 0; j < 5; j++) acc[j] += xv * sW2[k * C + j0 + j];
    }
    const float s = g_invout[n0 + n];
#pragma unroll
    for (int j = 0; j < 5; j++) g_h2[(size_t)(n0 + n) * C + j0 + j] = acc[j] * s;
}

// ---------------------------------------------------------------------------
// Aggregation layer 2 (gather) + norm + bias + log_softmax, fused, -> d_out.
__global__ void agg2_kernel(float* __restrict__ out, const float* __restrict__ b2) {
    const int n = (blockIdx.x * blockDim.x + threadIdx.x) >> 5;
    const int lane = threadIdx.x & 31;
    if (n >= N_NODES) return;
    const int start = g_off[n], end = g_off[n + 1];

    float acc0 = 0.f, acc1 = 0.f;
    int e = start;
    while (e + 32 <= end) {
        int sv = g_esrc[e + lane];
#pragma unroll
        for (int i = 0; i < 32; i++) {
            int s = __shfl_sync(0xffffffffu, sv, i);
            acc0 += g_h2[(size_t)s * C + lane];
            if (lane < 8) acc1 += g_h2[(size_t)s * C + 32 + lane];
        }
        e += 32;
    }
    if (e < end) {
        int rem = end - e;
        int sv = (lane < rem) ? g_esrc[e + lane] : 0;
        for (int i = 0; i < rem; i++) {
            int s = __shfl_sync(0xffffffffu, sv, i);
            acc0 += g_h2[(size_t)s * C + lane];
            if (lane < 8) acc1 += g_h2[(size_t)s * C + 32 + lane];
        }
    }

    const float inv = g_invin[n];
    const float NEG_INF = __int_as_float(0xff800000);
    float v0 = acc0 * inv + b2[lane];
    float v1 = (lane < 8) ? (acc1 * inv + b2[32 + lane]) : NEG_INF;

    float m = fmaxf(v0, v1);
#pragma unroll
    for (int o = 16; o; o >>= 1) m = fmaxf(m, __shfl_xor_sync(0xffffffffu, m, o));
    float se = expf(v0 - m) + ((lane < 8) ? expf(v1 - m) : 0.f);
#pragma unroll
    for (int o = 16; o; o >>= 1) se += __shfl_xor_sync(0xffffffffu, se, o);
    const float ls = logf(se);

    float* row = out + (size_t)n * C;
    row[lane] = v0 - m - ls;
    if (lane < 8) row[32 + lane] = v1 - m - ls;
}

// ---------------------------------------------------------------------------
extern "C" void kernel_launch(void* const* d_in, const int* in_sizes, int n_in,
                              void* d_out, int out_size) {
    const float* x   = (const float*)d_in[0];
    const float* W1  = (const float*)d_in[1];
    const float* b1  = (const float*)d_in[2];
    const float* W2  = (const float*)d_in[3];
    const float* b2  = (const float*)d_in[4];
    const int*   src = (const int*)d_in[5];
    const int*   dst = (const int*)d_in[6];
    float* out = (float*)d_out;

    zero_deg_kernel<<<(N_NODES + 255) / 256, 256>>>();
    hist_kernel<<<(N_EDGES + 255) / 256, 256>>>(src, dst);
    invsqrt_kernel<<<(N_NODES + 255) / 256, 256>>>();
    scan_kernel<<<1, 1024>>>();
    reorder_kernel<<<(N_EDGES + 255) / 256, 256>>>(src, dst);
    gemm1_kernel<<<(N_NODES + TILE_N - 1) / TILE_N, 128>>>(x, W1);
    agg1_kernel<<<(N_NODES * 32 + 255) / 256, 256>>>(b1);
    gemm2_kernel<<<N_NODES / 32, 256>>>(W2);
    agg2_kernel<<<(N_NODES * 32 + 255) / 256, 256>>>(out, b2);
}

// round 5
// speedup vs baseline: 2.8279x; 1.4736x over previous
#include <cuda_runtime.h>
#include <math.h>

#define N_NODES 100000
#define N_EDGES 3200000
#define F_IN    256
#define U       32
#define C       40

#define SCAN_CH   512
#define SCAN_NB   ((N_NODES + SCAN_CH - 1) / SCAN_CH)   // 196

// ---- scratch (device globals; no allocations allowed) ----
__device__ int   g_degout_i[N_NODES];
__device__ int   g_degin_i[N_NODES];
__device__ float g_invout[N_NODES];
__device__ float g_invin[N_NODES];
__device__ int   g_part[SCAN_NB];        // per-chunk degree sums -> scanned bases
__device__ int   g_off[N_NODES + 1];     // CSR offsets by dst
__device__ int   g_cursor[N_NODES];      // fill cursors
__device__ int   g_esrc[N_EDGES];        // src ids sorted by dst
__device__ float g_h1[(size_t)N_NODES * U];   // (x * d_out^-1/2) @ W1
__device__ float g_h1r[(size_t)N_NODES * U];  // relu(layer1 out)
__device__ float g_h2[(size_t)N_NODES * C];   // (h1r * d_out^-1/2) @ W2

// ---------------------------------------------------------------------------
__global__ void zero_deg_kernel() {
    int i = blockIdx.x * blockDim.x + threadIdx.x;
    if (i < N_NODES) { g_degout_i[i] = 0; g_degin_i[i] = 0; }
}

__global__ void hist_kernel(const int* __restrict__ src, const int* __restrict__ dst) {
    int e = blockIdx.x * blockDim.x + threadIdx.x;
    if (e >= N_EDGES) return;
    atomicAdd(&g_degout_i[src[e]], 1);
    atomicAdd(&g_degin_i[dst[e]], 1);
}

__global__ void invsqrt_kernel() {
    int n = blockIdx.x * blockDim.x + threadIdx.x;
    if (n >= N_NODES) return;
    g_invout[n] = rsqrtf(fmaxf((float)g_degout_i[n], 1.0f));
    g_invin[n]  = rsqrtf(fmaxf((float)g_degin_i[n],  1.0f));
}

// ---------------------------------------------------------------------------
// Two-level scan: (1) per-chunk sums, (2) scan of chunk sums, (3) local scan
// + base -> offsets/cursors. All full-chip parallel.
__global__ void __launch_bounds__(SCAN_CH) scan_part_kernel() {
    __shared__ int sw[SCAN_CH / 32];
    const int t = threadIdx.x;
    const int i = blockIdx.x * SCAN_CH + t;
    int v = (i < N_NODES) ? g_degin_i[i] : 0;
#pragma unroll
    for (int o = 16; o; o >>= 1) v += __shfl_xor_sync(0xffffffffu, v, o);
    if ((t & 31) == 0) sw[t >> 5] = v;
    __syncthreads();
    if (t < SCAN_CH / 32) {
        int s = sw[t];
#pragma unroll
        for (int o = SCAN_CH / 64; o; o >>= 1) s += __shfl_xor_sync(0xffffffffu, s, o);
        if (t == 0) g_part[blockIdx.x] = s;
    }
}

__global__ void scan_mid_kernel() {
    __shared__ int s[256];
    const int t = threadIdx.x;     // 256 threads, SCAN_NB <= 256
    int v = (t < SCAN_NB) ? g_part[t] : 0;
    s[t] = v;
    __syncthreads();
#pragma unroll
    for (int off = 1; off < 256; off <<= 1) {
        int u = (t >= off) ? s[t - off] : 0;
        __syncthreads();
        s[t] += u;
        __syncthreads();
    }
    if (t < SCAN_NB) g_part[t] = s[t] - v;   // exclusive
}

__global__ void __launch_bounds__(SCAN_CH) scan_write_kernel() {
    __shared__ int s[SCAN_CH];
    const int t = threadIdx.x;
    const int i = blockIdx.x * SCAN_CH + t;
    int v = (i < N_NODES) ? g_degin_i[i] : 0;
    s[t] = v;
    __syncthreads();
#pragma unroll
    for (int off = 1; off < SCAN_CH; off <<= 1) {
        int u = (t >= off) ? s[t - off] : 0;
        __syncthreads();
        s[t] += u;
        __syncthreads();
    }
    if (i < N_NODES) {
        int off = g_part[blockIdx.x] + s[t] - v;   // exclusive + base
        g_off[i] = off;
        g_cursor[i] = off;
    }
    if (i == 0) g_off[N_NODES] = N_EDGES;
}

__global__ void reorder_kernel(const int* __restrict__ src, const int* __restrict__ dst) {
    int e = blockIdx.x * blockDim.x + threadIdx.x;
    if (e >= N_EDGES) return;
    int pos = atomicAdd(&g_cursor[dst[e]], 1);
    g_esrc[pos] = src[e];
}

// ---------------------------------------------------------------------------
// GEMM1: h1[n,u] = invout[n] * sum_k x[n,k]*W1[k,u]
// Register-blocked: block = 128 threads, tile = 64 nodes x 32 u, K tiled by 64.
#define TILE_N 64
#define KT     64
__global__ void __launch_bounds__(128) gemm1_kernel(const float* __restrict__ x,
                                                    const float* __restrict__ W1) {
    __shared__ float sX[TILE_N][KT + 1];
    __shared__ float sW[KT][U];

    const int t  = threadIdx.x;
    const int ug = t & 7;
    const int ng = t >> 3;
    const int n0 = blockIdx.x * TILE_N;

    float acc[4][4] = {};

    for (int k0 = 0; k0 < F_IN; k0 += KT) {
        for (int i = t; i < KT * U; i += 128)
            ((float*)sW)[i] = W1[k0 * U + i];
        for (int i = t; i < TILE_N * KT; i += 128) {
            int n = i >> 6;
            int k = i & (KT - 1);
            int gn = n0 + n;
            sX[n][k] = (gn < N_NODES) ? x[(size_t)gn * F_IN + k0 + k] : 0.f;
        }
        __syncthreads();
#pragma unroll
        for (int k = 0; k < KT; k++) {
            float4 w = *(const float4*)&sW[k][ug * 4];
            float xv0 = sX[ng * 4 + 0][k];
            float xv1 = sX[ng * 4 + 1][k];
            float xv2 = sX[ng * 4 + 2][k];
            float xv3 = sX[ng * 4 + 3][k];
            acc[0][0] += xv0 * w.x; acc[0][1] += xv0 * w.y; acc[0][2] += xv0 * w.z; acc[0][3] += xv0 * w.w;
            acc[1][0] += xv1 * w.x; acc[1][1] += xv1 * w.y; acc[1][2] += xv1 * w.z; acc[1][3] += xv1 * w.w;
            acc[2][0] += xv2 * w.x; acc[2][1] += xv2 * w.y; acc[2][2] += xv2 * w.z; acc[2][3] += xv2 * w.w;
            acc[3][0] += xv3 * w.x; acc[3][1] += xv3 * w.y; acc[3][2] += xv3 * w.z; acc[3][3] += xv3 * w.w;
        }
        __syncthreads();
    }

#pragma unroll
    for (int i = 0; i < 4; i++) {
        int n = n0 + ng * 4 + i;
        if (n < N_NODES) {
            float s = g_invout[n];
            float4 o;
            o.x = acc[i][0] * s; o.y = acc[i][1] * s;
            o.z = acc[i][2] * s; o.w = acc[i][3] * s;
            *(float4*)&g_h1[(size_t)n * U + ug * 4] = o;
        }
    }
}

// ---------------------------------------------------------------------------
// Aggregation layer 1 (gather over CSR) + norm + bias + relu, fused.
__global__ void agg1_kernel(const float* __restrict__ b1) {
    const int n = (blockIdx.x * blockDim.x + threadIdx.x) >> 5;
    const int lane = threadIdx.x & 31;
    if (n >= N_NODES) return;
    const int start = g_off[n], end = g_off[n + 1];

    float acc = 0.f;
    int e = start;
    while (e + 32 <= end) {
        int sv = g_esrc[e + lane];
        float a0 = 0.f, a1 = 0.f, a2 = 0.f, a3 = 0.f;
#pragma unroll
        for (int i = 0; i < 32; i += 4) {
            int s0 = __shfl_sync(0xffffffffu, sv, i);
            int s1 = __shfl_sync(0xffffffffu, sv, i + 1);
            int s2 = __shfl_sync(0xffffffffu, sv, i + 2);
            int s3 = __shfl_sync(0xffffffffu, sv, i + 3);
            a0 += g_h1[(size_t)s0 * U + lane];
            a1 += g_h1[(size_t)s1 * U + lane];
            a2 += g_h1[(size_t)s2 * U + lane];
            a3 += g_h1[(size_t)s3 * U + lane];
        }
        acc += (a0 + a1) + (a2 + a3);
        e += 32;
    }
    if (e < end) {
        int rem = end - e;
        int sv = (lane < rem) ? g_esrc[e + lane] : 0;
        for (int i = 0; i < rem; i++) {
            int s = __shfl_sync(0xffffffffu, sv, i);
            acc += g_h1[(size_t)s * U + lane];
        }
    }
    g_h1r[(size_t)n * U + lane] = fmaxf(acc * g_invin[n] + b1[lane], 0.f);
}

// ---------------------------------------------------------------------------
// GEMM2: h2[n,j] = invout[n] * sum_k h1r[n,k]*W2[k,j]   (K=32, J=40)
__global__ void __launch_bounds__(256) gemm2_kernel(const float* __restrict__ W2) {
    __shared__ float sH[32][U + 1];
    __shared__ float sW2[U * C];
    const int t = threadIdx.x;
    const int n0 = blockIdx.x * 32;

    for (int i = t; i < U * C; i += 256) sW2[i] = W2[i];
    for (int i = t; i < 32 * U; i += 256) {
        int n = i >> 5, k = i & 31;
        sH[n][k] = g_h1r[(size_t)(n0 + n) * U + k];
    }
    __syncthreads();

    const int n = t & 31;
    const int j0 = (t >> 5) * 5;
    float acc[5] = {};
#pragma unroll
    for (int k = 0; k < U; k++) {
        float xv = sH[n][k];
#pragma unroll
        for (int j = 0; j < 5; j++) acc[j] += xv * sW2[k * C + j0 + j];
    }
    const float s = g_invout[n0 + n];
#pragma unroll
    for (int j = 0; j < 5; j++) g_h2[(size_t)(n0 + n) * C + j0 + j] = acc[j] * s;
}

// ---------------------------------------------------------------------------
// Aggregation layer 2 (gather) + norm + bias + log_softmax, fused -> d_out.
__global__ void agg2_kernel(float* __restrict__ out, const float* __restrict__ b2) {
    const int n = (blockIdx.x * blockDim.x + threadIdx.x) >> 5;
    const int lane = threadIdx.x & 31;
    if (n >= N_NODES) return;
    const int start = g_off[n], end = g_off[n + 1];

    float acc0 = 0.f, acc1 = 0.f;
    int e = start;
    while (e + 32 <= end) {
        int sv = g_esrc[e + lane];
#pragma unroll
        for (int i = 0; i < 32; i++) {
            int s = __shfl_sync(0xffffffffu, sv, i);
            acc0 += g_h2[(size_t)s * C + lane];
            if (lane < 8) acc1 += g_h2[(size_t)s * C + 32 + lane];
        }
        e += 32;
    }
    if (e < end) {
        int rem = end - e;
        int sv = (lane < rem) ? g_esrc[e + lane] : 0;
        for (int i = 0; i < rem; i++) {
            int s = __shfl_sync(0xffffffffu, sv, i);
            acc0 += g_h2[(size_t)s * C + lane];
            if (lane < 8) acc1 += g_h2[(size_t)s * C + 32 + lane];
        }
    }

    const float inv = g_invin[n];
    const float NEG_INF = __int_as_float(0xff800000);
    float v0 = acc0 * inv + b2[lane];
    float v1 = (lane < 8) ? (acc1 * inv + b2[32 + lane]) : NEG_INF;

    float m = fmaxf(v0, v1);
#pragma unroll
    for (int o = 16; o; o >>= 1) m = fmaxf(m, __shfl_xor_sync(0xffffffffu, m, o));
    float se = expf(v0 - m) + ((lane < 8) ? expf(v1 - m) : 0.f);
#pragma unroll
    for (int o = 16; o; o >>= 1) se += __shfl_xor_sync(0xffffffffu, se, o);
    const float ls = logf(se);

    float* row = out + (size_t)n * C;
    row[lane] = v0 - m - ls;
    if (lane < 8) row[32 + lane] = v1 - m - ls;
}

// ---------------------------------------------------------------------------
extern "C" void kernel_launch(void* const* d_in, const int* in_sizes, int n_in,
                              void* d_out, int out_size) {
    const float* x   = (const float*)d_in[0];
    const float* W1  = (const float*)d_in[1];
    const float* b1  = (const float*)d_in[2];
    const float* W2  = (const float*)d_in[3];
    const float* b2  = (const float*)d_in[4];
    const int*   src = (const int*)d_in[5];
    const int*   dst = (const int*)d_in[6];
    float* out = (float*)d_out;

    zero_deg_kernel<<<(N_NODES + 255) / 256, 256>>>();
    hist_kernel<<<(N_EDGES + 255) / 256, 256>>>(src, dst);
    invsqrt_kernel<<<(N_NODES + 255) / 256, 256>>>();
    scan_part_kernel<<<SCAN_NB, SCAN_CH>>>();
    scan_mid_kernel<<<1, 256>>>();
    scan_write_kernel<<<SCAN_NB, SCAN_CH>>>();
    reorder_kernel<<<(N_EDGES + 255) / 256, 256>>>(src, dst);
    gemm1_kernel<<<(N_NODES + TILE_N - 1) / TILE_N, 128>>>(x, W1);
    agg1_kernel<<<(N_NODES * 32 + 255) / 256, 256>>>(b1);
    gemm2_kernel<<<N_NODES / 32, 256>>>(W2);
    agg2_kernel<<<(N_NODES * 32 + 255) / 256, 256>>>(out, b2);
}